// round 13
// baseline (speedup 1.0000x reference)
#include <cuda_runtime.h>

#define EPS 1e-5f
#define C_DIM 64
#define B_DIM 8
#define CTX_DIM 256
#define SETUP_BLOCKS 71   // 64 MLP + 7 boundary-search

// Fused modulation coefficients: [0..511]   = A[b][c] = gamma[c]*(1+scale[b][c])
//                                [512..1023]= B[b][c] = beta[c]*(1+scale[b][c]) + shift[b][c]
__device__ __align__(16) float g_coef[2 * B_DIM * C_DIM];
// g_bound[k] = first row whose batch >= k+1. batch(row) = #{k : bound[k] <= row}
__device__ int g_bound[B_DIM - 1];
// Monotone completion counter (+SETUP_BLOCKS per kernel execution).
__device__ unsigned int g_flag = 0;

// ---------------------------------------------------------------------------
// ONE kernel. Blocks 0..63: tiny MLP (one warp per (batch,channel) pair).
// Blocks 64..70: one block per batch boundary (257-way block search).
// Blocks 71+: LayerNorm(64)+FiLM with acquire-gate at the TOP, then the
// best-measured streaming body (8 lanes/row, 2 float4/lane, 2 rows/thread).
// ---------------------------------------------------------------------------
template <bool GUARD>
__global__ void __launch_bounds__(256)
fused_kernel(const float* __restrict__ x,
             const float* __restrict__ token,  // [8,256]
             const float* __restrict__ W,      // [128,256]
             const float* __restrict__ bvec,   // [128]
             const float* __restrict__ gamma,  // [64]
             const float* __restrict__ beta,   // [64]
             const int* __restrict__ coors,    // [N,4] int32, col 0 sorted
             float* __restrict__ out,
             int n_rows)
{
    const int tid  = threadIdx.x;
    const int warp = tid >> 5;
    const int lane = tid & 31;

    if (blockIdx.x < SETUP_BLOCKS) {
        if (blockIdx.x < 64) {
            // ---- MLP: warp wg handles (batch j, channel c) ----
            const int wg = blockIdx.x * 8 + warp;   // 0..511
            const int j = wg >> 6;
            const int c = wg & 63;

            const float* trow = token + j * CTX_DIM;
            const float* wsh  = W + c * CTX_DIM;
            const float* wsc  = W + (C_DIM + c) * CTX_DIM;

            float tv[8], wa[8], wb[8];
#pragma unroll
            for (int i = 0; i < 8; ++i) {
                const int k = lane + 32 * i;
                tv[i] = __ldg(trow + k);
                wa[i] = __ldg(wsh + k);
                wb[i] = __ldg(wsc + k);
            }
            float acc_sh = 0.0f, acc_sc = 0.0f;
#pragma unroll
            for (int i = 0; i < 8; ++i) {
                const float s = tv[i] / (1.0f + expf(-tv[i]));
                acc_sh += s * wa[i];
                acc_sc += s * wb[i];
            }
#pragma unroll
            for (int o = 16; o >= 1; o >>= 1) {
                acc_sh += __shfl_xor_sync(0xffffffffu, acc_sh, o);
                acc_sc += __shfl_xor_sync(0xffffffffu, acc_sc, o);
            }
            if (lane == 0) {
                const float shift = acc_sh + bvec[c];
                const float scale = acc_sc + bvec[C_DIM + c];
                g_coef[j * C_DIM + c]                 = gamma[c] * (1.0f + scale);
                g_coef[B_DIM * C_DIM + j * C_DIM + c] = beta[c] * (1.0f + scale) + shift;
            }
        } else {
            // ---- Boundary search: block (64+k-1) finds lower_bound(batch >= k) ----
            __shared__ int s_lo, s_hi;
            const int k = (int)blockIdx.x - 63;      // 1..7
            if (tid == 0) { s_lo = 0; s_hi = n_rows; }
            __syncthreads();

            while (s_hi - s_lo > 256) {
                const int lo = s_lo, hi = s_hi;
                const long long len = hi - lo;
                const int pos = lo + (int)(((long long)(tid + 1) * len) / 257);
                const bool ge = __ldg(coors + (long long)pos * 4) >= k;
                const int posL = lo + (int)(((long long)tid * len) / 257);
                const bool geL = (tid == 0) ? false
                                            : (__ldg(coors + (long long)posL * 4) >= k);
                __syncthreads();
                if (ge && !geL) {
                    s_lo = (tid == 0) ? lo : posL;
                    s_hi = pos;
                }
                if (tid == 255 && !ge) s_lo = pos;
                __syncthreads();
            }
            __shared__ int s_ans;
            if (tid == 0) s_ans = s_hi;
            __syncthreads();
            const int lo = s_lo, hi = s_hi;
            const int pos = lo + tid;
            if (pos < hi && __ldg(coors + (long long)pos * 4) >= k) {
                atomicMin(&s_ans, pos);
            }
            __syncthreads();
            if (tid == 0) g_bound[k - 1] = s_ans;
        }
        __syncthreads();
        if (tid == 0) {
            __threadfence();                 // release: coef/bound visible first
            atomicAdd(&g_flag, 1u);
        }
        return;
    }

    // ------------------- Norm role: gate FIRST, then unsplit streaming body --
    __shared__ float sA[B_DIM * C_DIM];
    __shared__ float sB[B_DIM * C_DIM];
    __shared__ int sbnd[B_DIM - 1];

    if (tid == 0) {
        unsigned f;
        asm volatile("ld.acquire.gpu.global.u32 %0, [%1];"
                     : "=r"(f) : "l"(&g_flag) : "memory");
        while (f < SETUP_BLOCKS) {
            __nanosleep(128);
            asm volatile("ld.acquire.gpu.global.u32 %0, [%1];"
                         : "=r"(f) : "l"(&g_flag) : "memory");
        }
    }
    __syncthreads();

    for (int i = tid; i < B_DIM * C_DIM; i += 256) {
        sA[i] = g_coef[i];
        sB[i] = g_coef[B_DIM * C_DIM + i];
    }
    if (tid < B_DIM - 1) sbnd[tid] = g_bound[tid];
    __syncthreads();

    int bnd[B_DIM - 1];
#pragma unroll
    for (int k = 0; k < B_DIM - 1; ++k) bnd[k] = sbnd[k];

    const int g   = lane >> 3;   // row slot 0..3 within warp
    const int sub = lane & 7;    // lane within row

    const int base  = (int)(blockIdx.x - SETUP_BLOCKS) * 64 + warp * 8 + g;
    const int rows0 = base;
    const int rows1 = base + 4;
    const bool ok0 = !GUARD || rows0 < n_rows;
    const bool ok1 = !GUARD || rows1 < n_rows;

    const float4 z = make_float4(0.f, 0.f, 0.f, 0.f);
    const float4* p0 = reinterpret_cast<const float4*>(x) + (long long)rows0 * 16;
    const float4* p1 = reinterpret_cast<const float4*>(x) + (long long)rows1 * 16;
    float4 v00 = ok0 ? __ldcs(p0 + sub)     : z;
    float4 v01 = ok0 ? __ldcs(p0 + sub + 8) : z;
    float4 v10 = ok1 ? __ldcs(p1 + sub)     : z;
    float4 v11 = ok1 ? __ldcs(p1 + sub + 8) : z;

    float s0  = (v00.x + v00.y) + (v00.z + v00.w) + (v01.x + v01.y) + (v01.z + v01.w);
    float s20 = v00.x * v00.x + v00.y * v00.y + v00.z * v00.z + v00.w * v00.w
              + v01.x * v01.x + v01.y * v01.y + v01.z * v01.z + v01.w * v01.w;
    float s1  = (v10.x + v10.y) + (v10.z + v10.w) + (v11.x + v11.y) + (v11.z + v11.w);
    float s21 = v10.x * v10.x + v10.y * v10.y + v10.z * v10.z + v10.w * v10.w
              + v11.x * v11.x + v11.y * v11.y + v11.z * v11.z + v11.w * v11.w;

#pragma unroll
    for (int o = 4; o >= 1; o >>= 1) {
        s0  += __shfl_xor_sync(0xffffffffu, s0,  o);
        s20 += __shfl_xor_sync(0xffffffffu, s20, o);
        s1  += __shfl_xor_sync(0xffffffffu, s1,  o);
        s21 += __shfl_xor_sync(0xffffffffu, s21, o);
    }

    if (ok0) {
        const float mu  = s0 * (1.0f / 64.0f);
        const float var = s20 * (1.0f / 64.0f) - mu * mu;
        const float rs  = rsqrtf(var + EPS);
        int b = 0;
#pragma unroll
        for (int k = 0; k < B_DIM - 1; ++k) b += (rows0 >= bnd[k]);
        const float4* ap = reinterpret_cast<const float4*>(sA + b * C_DIM);
        const float4* bp = reinterpret_cast<const float4*>(sB + b * C_DIM);
        const float4 a0 = ap[sub], a1 = ap[sub + 8];
        const float4 b0 = bp[sub], b1 = bp[sub + 8];
        float4* po = reinterpret_cast<float4*>(out) + (long long)rows0 * 16;
        float4 o0, o1;
        o0.x = (v00.x - mu) * rs * a0.x + b0.x;
        o0.y = (v00.y - mu) * rs * a0.y + b0.y;
        o0.z = (v00.z - mu) * rs * a0.z + b0.z;
        o0.w = (v00.w - mu) * rs * a0.w + b0.w;
        o1.x = (v01.x - mu) * rs * a1.x + b1.x;
        o1.y = (v01.y - mu) * rs * a1.y + b1.y;
        o1.z = (v01.z - mu) * rs * a1.z + b1.z;
        o1.w = (v01.w - mu) * rs * a1.w + b1.w;
        __stcs(po + sub, o0);
        __stcs(po + sub + 8, o1);
    }
    if (ok1) {
        const float mu  = s1 * (1.0f / 64.0f);
        const float var = s21 * (1.0f / 64.0f) - mu * mu;
        const float rs  = rsqrtf(var + EPS);
        int b = 0;
#pragma unroll
        for (int k = 0; k < B_DIM - 1; ++k) b += (rows1 >= bnd[k]);
        const float4* ap = reinterpret_cast<const float4*>(sA + b * C_DIM);
        const float4* bp = reinterpret_cast<const float4*>(sB + b * C_DIM);
        const float4 a0 = ap[sub], a1 = ap[sub + 8];
        const float4 b0 = bp[sub], b1 = bp[sub + 8];
        float4* po = reinterpret_cast<float4*>(out) + (long long)rows1 * 16;
        float4 o0, o1;
        o0.x = (v10.x - mu) * rs * a0.x + b0.x;
        o0.y = (v10.y - mu) * rs * a0.y + b0.y;
        o0.z = (v10.z - mu) * rs * a0.z + b0.z;
        o0.w = (v10.w - mu) * rs * a0.w + b0.w;
        o1.x = (v11.x - mu) * rs * a1.x + b1.x;
        o1.y = (v11.y - mu) * rs * a1.y + b1.y;
        o1.z = (v11.z - mu) * rs * a1.z + b1.z;
        o1.w = (v11.w - mu) * rs * a1.w + b1.w;
        __stcs(po + sub, o0);
        __stcs(po + sub + 8, o1);
    }
}

// ---------------------------------------------------------------------------
// Launch. Inputs (metadata order): x, dataset_token, gamma, beta, W, b, coors
// ---------------------------------------------------------------------------
extern "C" void kernel_launch(void* const* d_in, const int* in_sizes, int n_in,
                              void* d_out, int out_size)
{
    const float* x      = (const float*)d_in[0];
    const float* token  = (const float*)d_in[1];
    const float* gamma  = (const float*)d_in[2];
    const float* beta   = (const float*)d_in[3];
    const float* W      = (const float*)d_in[4];
    const float* bvec   = (const float*)d_in[5];
    const int*   coors  = (const int*)d_in[6];
    float* out = (float*)d_out;

    const int n_rows = in_sizes[0] / C_DIM;
    const int norm_blocks = (n_rows + 63) / 64;
    const int grid = SETUP_BLOCKS + norm_blocks;

    if (n_rows % 64 == 0) {
        fused_kernel<false><<<grid, 256>>>(x, token, W, bvec, gamma, beta, coors, out, n_rows);
    } else {
        fused_kernel<true><<<grid, 256>>>(x, token, W, bvec, gamma, beta, coors, out, n_rows);
    }
}

// round 14
// speedup vs baseline: 1.0198x; 1.0198x over previous
#include <cuda_runtime.h>

#define EPS 1e-5f
#define C_DIM 64
#define B_DIM 8
#define CTX_DIM 256

// Fused modulation coefficients: [0..511]   = A[b][c] = gamma[c]*(1+scale[b][c])
//                                [512..1023]= B[b][c] = beta[c]*(1+scale[b][c]) + shift[b][c]
__device__ __align__(16) float g_coef[2 * B_DIM * C_DIM];
// g_bound[k] = first row whose batch >= k+1. batch(row) = #{k : bound[k] <= row}
__device__ int g_bound[B_DIM - 1];

// ---------------------------------------------------------------------------
// Setup kernel: blocks 0..63 = tiny MLP (one warp per (batch,channel) pair);
// blocks 64..70 = one block per batch boundary. Search does a 2049-way split
// (8 independent probes/thread) -> only TWO dependent memory rounds:
// 1M -> ~488 -> exact.
// ---------------------------------------------------------------------------
__global__ void __launch_bounds__(256)
setup_kernel(const float* __restrict__ token,  // [8,256]
             const float* __restrict__ W,      // [128,256]
             const float* __restrict__ bvec,   // [128]
             const float* __restrict__ gamma,  // [64]
             const float* __restrict__ beta,   // [64]
             const int* __restrict__ coors,    // [N,4] int32, col 0 sorted
             int n_rows)
{
    cudaTriggerProgrammaticLaunchCompletion();

    const int tid  = threadIdx.x;
    const int warp = tid >> 5;
    const int lane = tid & 31;

    if (blockIdx.x < 64) {
        const int wg = blockIdx.x * 8 + warp;   // 0..511
        const int j = wg >> 6;
        const int c = wg & 63;

        const float* trow = token + j * CTX_DIM;
        const float* wsh  = W + c * CTX_DIM;
        const float* wsc  = W + (C_DIM + c) * CTX_DIM;

        float tv[8], wa[8], wb[8];
#pragma unroll
        for (int i = 0; i < 8; ++i) {
            const int k = lane + 32 * i;
            tv[i] = __ldg(trow + k);
            wa[i] = __ldg(wsh + k);
            wb[i] = __ldg(wsc + k);
        }
        float acc_sh = 0.0f, acc_sc = 0.0f;
#pragma unroll
        for (int i = 0; i < 8; ++i) {
            const float s = tv[i] / (1.0f + expf(-tv[i]));
            acc_sh += s * wa[i];
            acc_sc += s * wb[i];
        }
#pragma unroll
        for (int o = 16; o >= 1; o >>= 1) {
            acc_sh += __shfl_xor_sync(0xffffffffu, acc_sh, o);
            acc_sc += __shfl_xor_sync(0xffffffffu, acc_sc, o);
        }
        if (lane == 0) {
            const float shift = acc_sh + bvec[c];
            const float scale = acc_sc + bvec[C_DIM + c];
            g_coef[j * C_DIM + c]                 = gamma[c] * (1.0f + scale);
            g_coef[B_DIM * C_DIM + j * C_DIM + c] = beta[c] * (1.0f + scale) + shift;
        }
    } else {
        // ---- Boundary search for batch k = blockIdx.x - 63 (1..7) ----
        __shared__ int s_lo, s_hi, s_first;
        const int k = (int)blockIdx.x - 63;
        if (tid == 0) { s_lo = 0; s_hi = n_rows; }
        __syncthreads();

        // Wide rounds: 2048 probes (8/thread), 2049-way split, until <=2048.
        while (s_hi - s_lo > 2048) {
            const int lo = s_lo, hi = s_hi;
            const long long len = hi - lo;
            if (tid == 0) s_first = 2048;
            __syncthreads();
            int idxs[8], poss[8];
            bool ges[8];
#pragma unroll
            for (int j = 0; j < 8; ++j) {
                idxs[j] = tid * 8 + j;                         // 0..2047
                poss[j] = lo + (int)(((long long)(idxs[j] + 1) * len) / 2049);
                ges[j]  = __ldg(coors + (long long)poss[j] * 4) >= k;
            }
#pragma unroll
            for (int j = 0; j < 8; ++j)
                if (ges[j]) atomicMin(&s_first, idxs[j]);
            __syncthreads();
            const int f = s_first;
            if (tid == 0) {
                if (f == 2048) {
                    // all probes < k: answer in (pos(2047), hi]
                    s_lo = lo + (int)((2048LL * len) / 2049) + 1;
                } else {
                    // answer in (pos(f-1), pos(f)]
                    if (f > 0) s_lo = lo + (int)(((long long)f * len) / 2049) + 1;
                    s_hi = lo + (int)(((long long)(f + 1) * len) / 2049);
                }
            }
            __syncthreads();
        }

        // Exact round: <=2048 candidates, 8 probes/thread.
        __shared__ int s_ans;
        if (tid == 0) s_ans = s_hi;
        __syncthreads();
        const int lo = s_lo, hi = s_hi;
#pragma unroll
        for (int j = 0; j < 8; ++j) {
            const int pos = lo + tid * 8 + j;
            if (pos < hi && __ldg(coors + (long long)pos * 4) >= k) {
                atomicMin(&s_ans, pos);
            }
        }
        __syncthreads();
        if (tid == 0) g_bound[k - 1] = s_ans;
    }
}

// ---------------------------------------------------------------------------
// Norm kernel — best-measured body: 8 lanes/row, 2 float4/lane, 2 rows/thread;
// block covers 64 rows. PDL wait at top. 32-bit byte offsets (x,out < 2^31 B).
// ---------------------------------------------------------------------------
template <bool GUARD>
__global__ void __launch_bounds__(256)
norm_mod_kernel(const float* __restrict__ x,
                float* __restrict__ out,
                int n_rows)
{
    __shared__ float sA[B_DIM * C_DIM];
    __shared__ float sB[B_DIM * C_DIM];
    __shared__ int sbnd[B_DIM - 1];

    cudaGridDependencySynchronize();

    const int tid = threadIdx.x;
    for (int i = tid; i < B_DIM * C_DIM; i += 256) {
        sA[i] = g_coef[i];
        sB[i] = g_coef[B_DIM * C_DIM + i];
    }
    if (tid < B_DIM - 1) sbnd[tid] = g_bound[tid];
    __syncthreads();

    int bnd[B_DIM - 1];
#pragma unroll
    for (int k = 0; k < B_DIM - 1; ++k) bnd[k] = sbnd[k];

    const int warp = tid >> 5;
    const int lane = tid & 31;
    const int g    = lane >> 3;   // row slot 0..3 within warp
    const int sub  = lane & 7;    // lane within row

    const int base  = blockIdx.x * 64 + warp * 8 + g;
    const int rows0 = base;
    const int rows1 = base + 4;
    const bool ok0 = !GUARD || rows0 < n_rows;
    const bool ok1 = !GUARD || rows1 < n_rows;

    // 32-bit element offsets (float4 units); max 16M < 2^31.
    const unsigned off0 = (unsigned)rows0 * 16u + (unsigned)sub;
    const unsigned off1 = off0 + 64u;   // +4 rows

    const float4 z = make_float4(0.f, 0.f, 0.f, 0.f);
    const float4* px = reinterpret_cast<const float4*>(x);
    float4 v00 = ok0 ? __ldcs(px + off0)     : z;
    float4 v01 = ok0 ? __ldcs(px + off0 + 8) : z;
    float4 v10 = ok1 ? __ldcs(px + off1)     : z;
    float4 v11 = ok1 ? __ldcs(px + off1 + 8) : z;

    float s0  = (v00.x + v00.y) + (v00.z + v00.w) + (v01.x + v01.y) + (v01.z + v01.w);
    float s20 = v00.x * v00.x + v00.y * v00.y + v00.z * v00.z + v00.w * v00.w
              + v01.x * v01.x + v01.y * v01.y + v01.z * v01.z + v01.w * v01.w;
    float s1  = (v10.x + v10.y) + (v10.z + v10.w) + (v11.x + v11.y) + (v11.z + v11.w);
    float s21 = v10.x * v10.x + v10.y * v10.y + v10.z * v10.z + v10.w * v10.w
              + v11.x * v11.x + v11.y * v11.y + v11.z * v11.z + v11.w * v11.w;

#pragma unroll
    for (int o = 4; o >= 1; o >>= 1) {
        s0  += __shfl_xor_sync(0xffffffffu, s0,  o);
        s20 += __shfl_xor_sync(0xffffffffu, s20, o);
        s1  += __shfl_xor_sync(0xffffffffu, s1,  o);
        s21 += __shfl_xor_sync(0xffffffffu, s21, o);
    }

    float4* pout = reinterpret_cast<float4*>(out);

    if (ok0) {
        const float mu  = s0 * (1.0f / 64.0f);
        const float var = s20 * (1.0f / 64.0f) - mu * mu;
        const float rs  = rsqrtf(var + EPS);
        int b = 0;
#pragma unroll
        for (int k = 0; k < B_DIM - 1; ++k) b += (rows0 >= bnd[k]);
        const float4* ap = reinterpret_cast<const float4*>(sA + b * C_DIM);
        const float4* bp = reinterpret_cast<const float4*>(sB + b * C_DIM);
        const float4 a0 = ap[sub], a1 = ap[sub + 8];
        const float4 b0 = bp[sub], b1 = bp[sub + 8];
        float4 o0, o1;
        o0.x = (v00.x - mu) * rs * a0.x + b0.x;
        o0.y = (v00.y - mu) * rs * a0.y + b0.y;
        o0.z = (v00.z - mu) * rs * a0.z + b0.z;
        o0.w = (v00.w - mu) * rs * a0.w + b0.w;
        o1.x = (v01.x - mu) * rs * a1.x + b1.x;
        o1.y = (v01.y - mu) * rs * a1.y + b1.y;
        o1.z = (v01.z - mu) * rs * a1.z + b1.z;
        o1.w = (v01.w - mu) * rs * a1.w + b1.w;
        __stcs(pout + off0, o0);
        __stcs(pout + off0 + 8, o1);
    }
    if (ok1) {
        const float mu  = s1 * (1.0f / 64.0f);
        const float var = s21 * (1.0f / 64.0f) - mu * mu;
        const float rs  = rsqrtf(var + EPS);
        int b = 0;
#pragma unroll
        for (int k = 0; k < B_DIM - 1; ++k) b += (rows1 >= bnd[k]);
        const float4* ap = reinterpret_cast<const float4*>(sA + b * C_DIM);
        const float4* bp = reinterpret_cast<const float4*>(sB + b * C_DIM);
        const float4 a0 = ap[sub], a1 = ap[sub + 8];
        const float4 b0 = bp[sub], b1 = bp[sub + 8];
        float4 o0, o1;
        o0.x = (v10.x - mu) * rs * a0.x + b0.x;
        o0.y = (v10.y - mu) * rs * a0.y + b0.y;
        o0.z = (v10.z - mu) * rs * a0.z + b0.z;
        o0.w = (v10.w - mu) * rs * a0.w + b0.w;
        o1.x = (v11.x - mu) * rs * a1.x + b1.x;
        o1.y = (v11.y - mu) * rs * a1.y + b1.y;
        o1.z = (v11.z - mu) * rs * a1.z + b1.z;
        o1.w = (v11.w - mu) * rs * a1.w + b1.w;
        __stcs(pout + off1, o0);
        __stcs(pout + off1 + 8, o1);
    }
}

// ---------------------------------------------------------------------------
// Launch. Inputs (metadata order): x, dataset_token, gamma, beta, W, b, coors
// Norm kernel launched with Programmatic Stream Serialization (PDL).
// ---------------------------------------------------------------------------
extern "C" void kernel_launch(void* const* d_in, const int* in_sizes, int n_in,
                              void* d_out, int out_size)
{
    const float* x      = (const float*)d_in[0];
    const float* token  = (const float*)d_in[1];
    const float* gamma  = (const float*)d_in[2];
    const float* beta   = (const float*)d_in[3];
    const float* W      = (const float*)d_in[4];
    const float* bvec   = (const float*)d_in[5];
    const int*   coors  = (const int*)d_in[6];
    float* out = (float*)d_out;

    const int n_rows = in_sizes[0] / C_DIM;
    const int grid = (n_rows + 63) / 64;

    setup_kernel<<<64 + (B_DIM - 1), 256>>>(token, W, bvec, gamma, beta, coors, n_rows);

    cudaLaunchConfig_t cfg = {};
    cfg.gridDim = dim3((unsigned)grid, 1, 1);
    cfg.blockDim = dim3(256, 1, 1);
    cfg.dynamicSmemBytes = 0;
    cfg.stream = 0;
    cudaLaunchAttribute attrs[1];
    attrs[0].id = cudaLaunchAttributeProgrammaticStreamSerialization;
    attrs[0].val.programmaticStreamSerializationAllowed = 1;
    cfg.attrs = attrs;
    cfg.numAttrs = 1;

    if (n_rows % 64 == 0) {
        cudaLaunchKernelEx(&cfg, norm_mod_kernel<false>, x, out, n_rows);
    } else {
        cudaLaunchKernelEx(&cfg, norm_mod_kernel<true>, x, out, n_rows);
    }
}

// round 15
// speedup vs baseline: 1.0381x; 1.0179x over previous
#include <cuda_runtime.h>

#define EPS 1e-5f
#define C_DIM 64
#define B_DIM 8
#define CTX_DIM 256

// Fused modulation coefficients: [0..511]   = A[b][c] = gamma[c]*(1+scale[b][c])
//                                [512..1023]= B[b][c] = beta[c]*(1+scale[b][c]) + shift[b][c]
__device__ __align__(16) float g_coef[2 * B_DIM * C_DIM];

// ---------------------------------------------------------------------------
// Setup kernel: ONLY the tiny MLP now (one warp per (batch,channel) pair).
// 64 blocks, no dependent-load search rounds -> ~1us critical path.
// ---------------------------------------------------------------------------
__global__ void __launch_bounds__(256)
setup_kernel(const float* __restrict__ token,  // [8,256]
             const float* __restrict__ W,      // [128,256]
             const float* __restrict__ bvec,   // [128]
             const float* __restrict__ gamma,  // [64]
             const float* __restrict__ beta)   // [64]
{
    cudaTriggerProgrammaticLaunchCompletion();

    const int warp = threadIdx.x >> 5;
    const int lane = threadIdx.x & 31;

    const int wg = blockIdx.x * 8 + warp;   // 0..511
    const int j = wg >> 6;                  // batch
    const int c = wg & 63;                  // channel

    const float* trow = token + j * CTX_DIM;
    const float* wsh  = W + c * CTX_DIM;
    const float* wsc  = W + (C_DIM + c) * CTX_DIM;

    float tv[8], wa[8], wb[8];
#pragma unroll
    for (int i = 0; i < 8; ++i) {
        const int k = lane + 32 * i;
        tv[i] = __ldg(trow + k);
        wa[i] = __ldg(wsh + k);
        wb[i] = __ldg(wsc + k);
    }
    float acc_sh = 0.0f, acc_sc = 0.0f;
#pragma unroll
    for (int i = 0; i < 8; ++i) {
        const float s = tv[i] / (1.0f + expf(-tv[i]));
        acc_sh += s * wa[i];
        acc_sc += s * wb[i];
    }
#pragma unroll
    for (int o = 16; o >= 1; o >>= 1) {
        acc_sh += __shfl_xor_sync(0xffffffffu, acc_sh, o);
        acc_sc += __shfl_xor_sync(0xffffffffu, acc_sc, o);
    }
    if (lane == 0) {
        const float shift = acc_sh + bvec[c];
        const float scale = acc_sc + bvec[C_DIM + c];
        g_coef[j * C_DIM + c]                 = gamma[c] * (1.0f + scale);
        g_coef[B_DIM * C_DIM + j * C_DIM + c] = beta[c] * (1.0f + scale) + shift;
    }
}

// ---------------------------------------------------------------------------
// Norm kernel — R14 body (best: 74.3us) + self-service batch index:
// two threads read coors at the block's first/last row BEFORE the PDL gate
// (latency hidden behind the wait). If equal (all but <=7 blocks), every row
// uses that b; else per-row fallback read. No boundary search anywhere.
// 8 lanes/row, 2 float4/lane, 2 rows/thread; block covers 64 rows.
// ---------------------------------------------------------------------------
template <bool GUARD>
__global__ void __launch_bounds__(256)
norm_mod_kernel(const float* __restrict__ x,
                const int* __restrict__ coors,   // [N,4] int32, col 0 sorted
                float* __restrict__ out,
                int n_rows)
{
    __shared__ float sA[B_DIM * C_DIM];
    __shared__ float sB[B_DIM * C_DIM];
    __shared__ int sb_first, sb_last;

    const int tid = threadIdx.x;
    const int blk_row0 = blockIdx.x * 64;
    int blk_rowN = blk_row0 + 63;
    if (GUARD && blk_rowN >= n_rows) blk_rowN = n_rows - 1;

    // Issue batch-index probes BEFORE the gate (independent of setup).
    if (tid == 0) sb_first = coors[(long long)blk_row0 * 4];
    if (tid == 32) sb_last = coors[(long long)blk_rowN * 4];

    cudaGridDependencySynchronize();

    for (int i = tid; i < B_DIM * C_DIM; i += 256) {
        sA[i] = g_coef[i];
        sB[i] = g_coef[B_DIM * C_DIM + i];
    }
    __syncthreads();

    const bool uniform = (sb_first == sb_last);
    const int b_uni = sb_first;

    const int warp = tid >> 5;
    const int lane = tid & 31;
    const int g    = lane >> 3;   // row slot 0..3 within warp
    const int sub  = lane & 7;    // lane within row

    const int rows0 = blk_row0 + warp * 8 + g;
    const int rows1 = rows0 + 4;
    const bool ok0 = !GUARD || rows0 < n_rows;
    const bool ok1 = !GUARD || rows1 < n_rows;

    const unsigned off0 = (unsigned)rows0 * 16u + (unsigned)sub;
    const unsigned off1 = off0 + 64u;   // +4 rows

    const float4 z = make_float4(0.f, 0.f, 0.f, 0.f);
    const float4* px = reinterpret_cast<const float4*>(x);
    float4 v00 = ok0 ? __ldcs(px + off0)     : z;
    float4 v01 = ok0 ? __ldcs(px + off0 + 8) : z;
    float4 v10 = ok1 ? __ldcs(px + off1)     : z;
    float4 v11 = ok1 ? __ldcs(px + off1 + 8) : z;

    float s0  = (v00.x + v00.y) + (v00.z + v00.w) + (v01.x + v01.y) + (v01.z + v01.w);
    float s20 = v00.x * v00.x + v00.y * v00.y + v00.z * v00.z + v00.w * v00.w
              + v01.x * v01.x + v01.y * v01.y + v01.z * v01.z + v01.w * v01.w;
    float s1  = (v10.x + v10.y) + (v10.z + v10.w) + (v11.x + v11.y) + (v11.z + v11.w);
    float s21 = v10.x * v10.x + v10.y * v10.y + v10.z * v10.z + v10.w * v10.w
              + v11.x * v11.x + v11.y * v11.y + v11.z * v11.z + v11.w * v11.w;

#pragma unroll
    for (int o = 4; o >= 1; o >>= 1) {
        s0  += __shfl_xor_sync(0xffffffffu, s0,  o);
        s20 += __shfl_xor_sync(0xffffffffu, s20, o);
        s1  += __shfl_xor_sync(0xffffffffu, s1,  o);
        s21 += __shfl_xor_sync(0xffffffffu, s21, o);
    }

    // Batch indices: fast uniform path; rare per-row fallback (<=7 blocks).
    int b0 = b_uni, b1 = b_uni;
    if (!uniform) {
        if (ok0) b0 = coors[(long long)rows0 * 4];
        if (ok1) b1 = coors[(long long)rows1 * 4];
    }

    float4* pout = reinterpret_cast<float4*>(out);

    if (ok0) {
        const float mu  = s0 * (1.0f / 64.0f);
        const float var = s20 * (1.0f / 64.0f) - mu * mu;
        const float rs  = rsqrtf(var + EPS);
        const float4* ap = reinterpret_cast<const float4*>(sA + b0 * C_DIM);
        const float4* bp = reinterpret_cast<const float4*>(sB + b0 * C_DIM);
        const float4 a0 = ap[sub], a1 = ap[sub + 8];
        const float4 c0 = bp[sub], c1 = bp[sub + 8];
        float4 o0, o1;
        o0.x = (v00.x - mu) * rs * a0.x + c0.x;
        o0.y = (v00.y - mu) * rs * a0.y + c0.y;
        o0.z = (v00.z - mu) * rs * a0.z + c0.z;
        o0.w = (v00.w - mu) * rs * a0.w + c0.w;
        o1.x = (v01.x - mu) * rs * a1.x + c1.x;
        o1.y = (v01.y - mu) * rs * a1.y + c1.y;
        o1.z = (v01.z - mu) * rs * a1.z + c1.z;
        o1.w = (v01.w - mu) * rs * a1.w + c1.w;
        __stcs(pout + off0, o0);
        __stcs(pout + off0 + 8, o1);
    }
    if (ok1) {
        const float mu  = s1 * (1.0f / 64.0f);
        const float var = s21 * (1.0f / 64.0f) - mu * mu;
        const float rs  = rsqrtf(var + EPS);
        const float4* ap = reinterpret_cast<const float4*>(sA + b1 * C_DIM);
        const float4* bp = reinterpret_cast<const float4*>(sB + b1 * C_DIM);
        const float4 a0 = ap[sub], a1 = ap[sub + 8];
        const float4 c0 = bp[sub], c1 = bp[sub + 8];
        float4 o0, o1;
        o0.x = (v10.x - mu) * rs * a0.x + c0.x;
        o0.y = (v10.y - mu) * rs * a0.y + c0.y;
        o0.z = (v10.z - mu) * rs * a0.z + c0.z;
        o0.w = (v10.w - mu) * rs * a0.w + c0.w;
        o1.x = (v11.x - mu) * rs * a1.x + c1.x;
        o1.y = (v11.y - mu) * rs * a1.y + c1.y;
        o1.z = (v11.z - mu) * rs * a1.z + c1.z;
        o1.w = (v11.w - mu) * rs * a1.w + c1.w;
        __stcs(pout + off1, o0);
        __stcs(pout + off1 + 8, o1);
    }
}

// ---------------------------------------------------------------------------
// Launch. Inputs (metadata order): x, dataset_token, gamma, beta, W, b, coors
// Norm kernel launched with Programmatic Stream Serialization (PDL).
// ---------------------------------------------------------------------------
extern "C" void kernel_launch(void* const* d_in, const int* in_sizes, int n_in,
                              void* d_out, int out_size)
{
    const float* x      = (const float*)d_in[0];
    const float* token  = (const float*)d_in[1];
    const float* gamma  = (const float*)d_in[2];
    const float* beta   = (const float*)d_in[3];
    const float* W      = (const float*)d_in[4];
    const float* bvec   = (const float*)d_in[5];
    const int*   coors  = (const int*)d_in[6];
    float* out = (float*)d_out;

    const int n_rows = in_sizes[0] / C_DIM;
    const int grid = (n_rows + 63) / 64;

    setup_kernel<<<64, 256>>>(token, W, bvec, gamma, beta);

    cudaLaunchConfig_t cfg = {};
    cfg.gridDim = dim3((unsigned)grid, 1, 1);
    cfg.blockDim = dim3(256, 1, 1);
    cfg.dynamicSmemBytes = 0;
    cfg.stream = 0;
    cudaLaunchAttribute attrs[1];
    attrs[0].id = cudaLaunchAttributeProgrammaticStreamSerialization;
    attrs[0].val.programmaticStreamSerializationAllowed = 1;
    cfg.attrs = attrs;
    cfg.numAttrs = 1;

    if (n_rows % 64 == 0) {
        cudaLaunchKernelEx(&cfg, norm_mod_kernel<false>, x, coors, out, n_rows);
    } else {
        cudaLaunchKernelEx(&cfg, norm_mod_kernel<true>, x, coors, out, n_rows);
    }
}

// round 16
// speedup vs baseline: 1.0438x; 1.0055x over previous
#include <cuda_runtime.h>

#define EPS 1e-5f
#define C_DIM 64
#define B_DIM 8
#define CTX_DIM 256

// Fused modulation coefficients: [0..511]   = A[b][c] = gamma[c]*(1+scale[b][c])
//                                [512..1023]= B[b][c] = beta[c]*(1+scale[b][c]) + shift[b][c]
__device__ __align__(16) float g_coef[2 * B_DIM * C_DIM];
// g_bound[k] = first row whose batch >= k+1. batch(row) = #{k : bound[k] <= row}
__device__ int g_bound[B_DIM - 1];

// ---------------------------------------------------------------------------
// Setup kernel (R11 version — best measured gap): blocks 0..63 = tiny MLP
// (one warp per (batch,channel) pair); blocks 64..70 = one block per batch
// boundary, 257-way block-parallel search (3 dependent rounds).
// ---------------------------------------------------------------------------
__global__ void __launch_bounds__(256)
setup_kernel(const float* __restrict__ token,  // [8,256]
             const float* __restrict__ W,      // [128,256]
             const float* __restrict__ bvec,   // [128]
             const float* __restrict__ gamma,  // [64]
             const float* __restrict__ beta,   // [64]
             const int* __restrict__ coors,    // [N,4] int32, col 0 sorted
             int n_rows)
{
    cudaTriggerProgrammaticLaunchCompletion();

    const int tid  = threadIdx.x;
    const int warp = tid >> 5;
    const int lane = tid & 31;

    if (blockIdx.x < 64) {
        const int wg = blockIdx.x * 8 + warp;   // 0..511
        const int j = wg >> 6;
        const int c = wg & 63;

        const float* trow = token + j * CTX_DIM;
        const float* wsh  = W + c * CTX_DIM;
        const float* wsc  = W + (C_DIM + c) * CTX_DIM;

        float tv[8], wa[8], wb[8];
#pragma unroll
        for (int i = 0; i < 8; ++i) {
            const int k = lane + 32 * i;
            tv[i] = __ldg(trow + k);
            wa[i] = __ldg(wsh + k);
            wb[i] = __ldg(wsc + k);
        }
        float acc_sh = 0.0f, acc_sc = 0.0f;
#pragma unroll
        for (int i = 0; i < 8; ++i) {
            const float s = tv[i] / (1.0f + expf(-tv[i]));
            acc_sh += s * wa[i];
            acc_sc += s * wb[i];
        }
#pragma unroll
        for (int o = 16; o >= 1; o >>= 1) {
            acc_sh += __shfl_xor_sync(0xffffffffu, acc_sh, o);
            acc_sc += __shfl_xor_sync(0xffffffffu, acc_sc, o);
        }
        if (lane == 0) {
            const float shift = acc_sh + bvec[c];
            const float scale = acc_sc + bvec[C_DIM + c];
            g_coef[j * C_DIM + c]                 = gamma[c] * (1.0f + scale);
            g_coef[B_DIM * C_DIM + j * C_DIM + c] = beta[c] * (1.0f + scale) + shift;
        }
    } else {
        // ---- Boundary search: block (64+k-1) finds lower_bound(batch >= k) ----
        __shared__ int s_lo, s_hi;
        const int k = (int)blockIdx.x - 63;      // 1..7
        if (tid == 0) { s_lo = 0; s_hi = n_rows; }
        __syncthreads();

        while (s_hi - s_lo > 256) {
            const int lo = s_lo, hi = s_hi;
            const long long len = hi - lo;
            const int pos = lo + (int)(((long long)(tid + 1) * len) / 257);
            const bool ge = __ldg(coors + (long long)pos * 4) >= k;
            const int posL = lo + (int)(((long long)tid * len) / 257);
            const bool geL = (tid == 0) ? false
                                        : (__ldg(coors + (long long)posL * 4) >= k);
            __syncthreads();
            if (ge && !geL) {
                s_lo = (tid == 0) ? lo : posL;
                s_hi = pos;
            }
            if (tid == 255 && !ge) s_lo = pos;
            __syncthreads();
        }
        __shared__ int s_ans;
        if (tid == 0) s_ans = s_hi;
        __syncthreads();
        const int lo = s_lo, hi = s_hi;
        const int pos = lo + tid;
        if (pos < hi && __ldg(coors + (long long)pos * 4) >= k) {
            atomicMin(&s_ans, pos);
        }
        __syncthreads();
        if (tid == 0) g_bound[k - 1] = s_ans;
    }
}

// ---------------------------------------------------------------------------
// Norm kernel (R14 body — best measured: 74.3us, regs 38): 8 lanes/row,
// 2 float4/lane, 2 rows/thread; block covers 64 rows. PDL wait at top,
// 32-bit element offsets, batch index from 7 register compares.
// ---------------------------------------------------------------------------
template <bool GUARD>
__global__ void __launch_bounds__(256)
norm_mod_kernel(const float* __restrict__ x,
                float* __restrict__ out,
                int n_rows)
{
    __shared__ float sA[B_DIM * C_DIM];
    __shared__ float sB[B_DIM * C_DIM];
    __shared__ int sbnd[B_DIM - 1];

    cudaGridDependencySynchronize();

    const int tid = threadIdx.x;
    for (int i = tid; i < B_DIM * C_DIM; i += 256) {
        sA[i] = g_coef[i];
        sB[i] = g_coef[B_DIM * C_DIM + i];
    }
    if (tid < B_DIM - 1) sbnd[tid] = g_bound[tid];
    __syncthreads();

    int bnd[B_DIM - 1];
#pragma unroll
    for (int k = 0; k < B_DIM - 1; ++k) bnd[k] = sbnd[k];

    const int warp = tid >> 5;
    const int lane = tid & 31;
    const int g    = lane >> 3;   // row slot 0..3 within warp
    const int sub  = lane & 7;    // lane within row

    const int base  = blockIdx.x * 64 + warp * 8 + g;
    const int rows0 = base;
    const int rows1 = base + 4;
    const bool ok0 = !GUARD || rows0 < n_rows;
    const bool ok1 = !GUARD || rows1 < n_rows;

    const unsigned off0 = (unsigned)rows0 * 16u + (unsigned)sub;
    const unsigned off1 = off0 + 64u;   // +4 rows

    const float4 z = make_float4(0.f, 0.f, 0.f, 0.f);
    const float4* px = reinterpret_cast<const float4*>(x);
    float4 v00 = ok0 ? __ldcs(px + off0)     : z;
    float4 v01 = ok0 ? __ldcs(px + off0 + 8) : z;
    float4 v10 = ok1 ? __ldcs(px + off1)     : z;
    float4 v11 = ok1 ? __ldcs(px + off1 + 8) : z;

    float s0  = (v00.x + v00.y) + (v00.z + v00.w) + (v01.x + v01.y) + (v01.z + v01.w);
    float s20 = v00.x * v00.x + v00.y * v00.y + v00.z * v00.z + v00.w * v00.w
              + v01.x * v01.x + v01.y * v01.y + v01.z * v01.z + v01.w * v01.w;
    float s1  = (v10.x + v10.y) + (v10.z + v10.w) + (v11.x + v11.y) + (v11.z + v11.w);
    float s21 = v10.x * v10.x + v10.y * v10.y + v10.z * v10.z + v10.w * v10.w
              + v11.x * v11.x + v11.y * v11.y + v11.z * v11.z + v11.w * v11.w;

#pragma unroll
    for (int o = 4; o >= 1; o >>= 1) {
        s0  += __shfl_xor_sync(0xffffffffu, s0,  o);
        s20 += __shfl_xor_sync(0xffffffffu, s20, o);
        s1  += __shfl_xor_sync(0xffffffffu, s1,  o);
        s21 += __shfl_xor_sync(0xffffffffu, s21, o);
    }

    float4* pout = reinterpret_cast<float4*>(out);

    if (ok0) {
        const float mu  = s0 * (1.0f / 64.0f);
        const float var = s20 * (1.0f / 64.0f) - mu * mu;
        const float rs  = rsqrtf(var + EPS);
        int b = 0;
#pragma unroll
        for (int k = 0; k < B_DIM - 1; ++k) b += (rows0 >= bnd[k]);
        const float4* ap = reinterpret_cast<const float4*>(sA + b * C_DIM);
        const float4* bp = reinterpret_cast<const float4*>(sB + b * C_DIM);
        const float4 a0 = ap[sub], a1 = ap[sub + 8];
        const float4 b0 = bp[sub], b1 = bp[sub + 8];
        float4 o0, o1;
        o0.x = (v00.x - mu) * rs * a0.x + b0.x;
        o0.y = (v00.y - mu) * rs * a0.y + b0.y;
        o0.z = (v00.z - mu) * rs * a0.z + b0.z;
        o0.w = (v00.w - mu) * rs * a0.w + b0.w;
        o1.x = (v01.x - mu) * rs * a1.x + b1.x;
        o1.y = (v01.y - mu) * rs * a1.y + b1.y;
        o1.z = (v01.z - mu) * rs * a1.z + b1.z;
        o1.w = (v01.w - mu) * rs * a1.w + b1.w;
        __stcs(pout + off0, o0);
        __stcs(pout + off0 + 8, o1);
    }
    if (ok1) {
        const float mu  = s1 * (1.0f / 64.0f);
        const float var = s21 * (1.0f / 64.0f) - mu * mu;
        const float rs  = rsqrtf(var + EPS);
        int b = 0;
#pragma unroll
        for (int k = 0; k < B_DIM - 1; ++k) b += (rows1 >= bnd[k]);
        const float4* ap = reinterpret_cast<const float4*>(sA + b * C_DIM);
        const float4* bp = reinterpret_cast<const float4*>(sB + b * C_DIM);
        const float4 a0 = ap[sub], a1 = ap[sub + 8];
        const float4 b0 = bp[sub], b1 = bp[sub + 8];
        float4 o0, o1;
        o0.x = (v10.x - mu) * rs * a0.x + b0.x;
        o0.y = (v10.y - mu) * rs * a0.y + b0.y;
        o0.z = (v10.z - mu) * rs * a0.z + b0.z;
        o0.w = (v10.w - mu) * rs * a0.w + b0.w;
        o1.x = (v11.x - mu) * rs * a1.x + b1.x;
        o1.y = (v11.y - mu) * rs * a1.y + b1.y;
        o1.z = (v11.z - mu) * rs * a1.z + b1.z;
        o1.w = (v11.w - mu) * rs * a1.w + b1.w;
        __stcs(pout + off1, o0);
        __stcs(pout + off1 + 8, o1);
    }
}

// ---------------------------------------------------------------------------
// Launch. Inputs (metadata order): x, dataset_token, gamma, beta, W, b, coors
// Norm kernel launched with Programmatic Stream Serialization (PDL).
// ---------------------------------------------------------------------------
extern "C" void kernel_launch(void* const* d_in, const int* in_sizes, int n_in,
                              void* d_out, int out_size)
{
    const float* x      = (const float*)d_in[0];
    const float* token  = (const float*)d_in[1];
    const float* gamma  = (const float*)d_in[2];
    const float* beta   = (const float*)d_in[3];
    const float* W      = (const float*)d_in[4];
    const float* bvec   = (const float*)d_in[5];
    const int*   coors  = (const int*)d_in[6];
    float* out = (float*)d_out;

    const int n_rows = in_sizes[0] / C_DIM;
    const int grid = (n_rows + 63) / 64;

    setup_kernel<<<64 + (B_DIM - 1), 256>>>(token, W, bvec, gamma, beta, coors, n_rows);

    cudaLaunchConfig_t cfg = {};
    cfg.gridDim = dim3((unsigned)grid, 1, 1);
    cfg.blockDim = dim3(256, 1, 1);
    cfg.dynamicSmemBytes = 0;
    cfg.stream = 0;
    cudaLaunchAttribute attrs[1];
    attrs[0].id = cudaLaunchAttributeProgrammaticStreamSerialization;
    attrs[0].val.programmaticStreamSerializationAllowed = 1;
    cfg.attrs = attrs;
    cfg.numAttrs = 1;

    if (n_rows % 64 == 0) {
        cudaLaunchKernelEx(&cfg, norm_mod_kernel<false>, x, out, n_rows);
    } else {
        cudaLaunchKernelEx(&cfg, norm_mod_kernel<true>, x, out, n_rows);
    }
}